// round 17
// baseline (speedup 1.0000x reference)
#include <cuda_runtime.h>

#define RES     96
#define CENTERF 48.0f
#define EPSF    1e-5f
#define NWARPS  32
#define RIM2    2209.0f

#define CAPS    (RES * RES)          // per-source entA capacity
#define CAPP    ((CAPS + 1) / 2)     // source-pair capacity (entW)

// ---- f32x2 helpers ----------------------------------------------------------
__device__ __forceinline__ unsigned long long pk2(float a, float b) {
    unsigned long long r;
    asm("mov.b64 %0, {%1, %2};" : "=l"(r) : "f"(a), "f"(b));
    return r;
}
__device__ __forceinline__ void unpk2(unsigned long long v, float& a, float& b) {
    asm("mov.b64 {%0, %1}, %2;" : "=f"(a), "=f"(b) : "l"(v));
}
#define ADD2(d, a, b) asm("add.rn.f32x2 %0, %1, %2;" : "=l"(d) : "l"(a), "l"(b))
#define MUL2(d, a, b) asm("mul.rn.f32x2 %0, %1, %2;" : "=l"(d) : "l"(a), "l"(b))
#define FMA2(d, a, b, c) \
    asm("fma.rn.f32x2 %0, %1, %2, %3;" : "=l"(d) : "l"(a), "l"(b), "l"(c))
#define RCP2(d, s) asm("{.reg .f32 lo, hi;\n\t" \
                       "mov.b64 {lo, hi}, %1;\n\t" \
                       "rcp.approx.ftz.f32 lo, lo;\n\t" \
                       "rcp.approx.ftz.f32 hi, hi;\n\t" \
                       "mov.b64 %0, {lo, hi};}" : "=l"(d) : "l"(s))

// ---------------------------------------------------------------------------
// Single kernel (R16 structure; prologue slimmed).
// Grid: 144 = 48 i-pairs x 3 adaptive 32-wide j-windows.  Block: 1024 threads,
// 32 warps splitting the source-pair list (~72 iters/warp at K~4608).
//
// SMEM (NOT pre-zeroed): entA[s] = float4(-bi,-bi,-bj,-bj);
//                        entW[p] = float4(w0,w0,w1,w1).
// After compaction, if K is odd one thread writes a safe dummy source at slot
// K (coords (0,0), weight 0) — its term is exactly 0 in the pair algebra.
// Inner loop per source pair (rows i0,i1 in the f32x2 lanes => 4 terms):
//   a = den(s0), b = den(s1)   (exact integer diffs, 2 roundings per den)
//   acc += (w0*b + w1*a) * rcp2(a*b)     -> 2 MUFU / 4 terms, full f32
// The 2*eps*sqrt(d2) cross term of the reference is dropped
// (relative contribution <= eps/z <= 1e-5 for interior targets).
// ---------------------------------------------------------------------------
__global__ void __launch_bounds__(1024, 1) fused_kernel(
    const float* __restrict__ b, float* __restrict__ out)
{
    extern __shared__ float4 sm[];
    float4* entA = sm;                    // CAPS  float4
    float4* entW = sm + CAPS;             // CAPP  float4
    __shared__ int   cnts[RES];
    __shared__ int   offs[RES];
    __shared__ int   sK;
    __shared__ float red[NWARPS * 64];

    const int tid  = threadIdx.x;
    const int wid  = tid >> 5;
    const int lane = tid & 31;

    // ---- window placement (input-independent) ----
    const int pp  = blockIdx.x / 3;
    const int g   = blockIdx.x % 3;
    const int i0  = 2 * pp;

    const int a0i = abs(i0 - 48);
    const int a1i = abs(i0 + 1 - 48);
    const int dmin = a0i < a1i ? a0i : a1i;
    int s_ = 2208 - dmin * dmin; if (s_ < 0) s_ = 0;
    const int wmax = (int)sqrtf((float)s_) + 1;   // over-estimate: safe
    int J0 = 48 - wmax; if (J0 < 0) J0 = 0;

    const int j   = J0 + 32 * g + lane;           // may exceed 95 (guarded)
    const float fi0 = (float)i0;
    const float fj  = (float)j;

    const float dic0 = fi0 - CENTERF;
    const float dic1 = dic0 + 1.0f;
    const float djc  = fj - CENTERF;
    const float r2_0 = dic0 * dic0 + djc * djc;   // exact integer-valued
    const float r2_1 = dic1 * dic1 + djc * djc;

    // Rim passthrough for uncovered columns j < J0 (provably rim).
    if (g == 0 && tid < RES && tid < J0) {
        out[i0 * RES + tid]       = b[i0 * RES + tid];
        out[(i0 + 1) * RES + tid] = b[(i0 + 1) * RES + tid];
    }

    // allrim blocks: write their (all-rim) covered targets and exit BEFORE
    // the compaction — they don't need the source list.
    const bool allrim = __all_sync(0xffffffffu,
                                   (r2_0 >= RIM2) && (r2_1 >= RIM2));
    const bool blk_allrim = __syncthreads_and(allrim);  // block-uniform anyway
    if (blk_allrim) {
        if (tid < 64) {
            const int k  = tid >> 5;
            const int l  = tid & 31;
            const int ii = i0 + k;
            const int jj = J0 + 32 * g + l;
            if (jj < RES) out[ii * RES + jj] = b[ii * RES + jj];
        }
        return;
    }

    // ---- Phase 1: compaction (row-major deterministic order; no pre-zero) ----
    {
        const int r0 = wid * 3;
        #pragma unroll
        for (int rr = 0; rr < 3; rr++) {
            const int row = r0 + rr;
            int c = 0;
            #pragma unroll
            for (int s = 0; s < 3; s++) {
                float v = b[row * RES + s * 32 + lane];
                c += __popc(__ballot_sync(0xffffffffu, v > 0.0f));
            }
            if (lane == 0) cnts[row] = c;
        }
    }
    __syncthreads();
    if (wid == 0) {                       // exclusive prefix over 96 counts
        int a0 = cnts[lane], a1 = cnts[lane + 32], a2 = cnts[lane + 64];
        int s0 = a0, s1 = a1, s2 = a2;
        #pragma unroll
        for (int d = 1; d < 32; d <<= 1) {
            int t0 = __shfl_up_sync(0xffffffffu, s0, d); if (lane >= d) s0 += t0;
            int t1 = __shfl_up_sync(0xffffffffu, s1, d); if (lane >= d) s1 += t1;
            int t2 = __shfl_up_sync(0xffffffffu, s2, d); if (lane >= d) s2 += t2;
        }
        s1 += __shfl_sync(0xffffffffu, s0, 31);
        s2 += __shfl_sync(0xffffffffu, s1, 31);
        offs[lane]      = s0 - a0;
        offs[lane + 32] = s1 - a1;
        offs[lane + 64] = s2 - a2;
        if (lane == 31) sK = s2;
    }
    __syncthreads();
    {
        const int r0 = wid * 3;
        #pragma unroll
        for (int rr = 0; rr < 3; rr++) {
            const int row = r0 + rr;
            int p = offs[row];
            #pragma unroll
            for (int s = 0; s < 3; s++) {
                const int col = s * 32 + lane;
                float v = b[row * RES + col];
                unsigned m = __ballot_sync(0xffffffffu, v > 0.0f);
                if (v > 0.0f) {
                    int pos = p + __popc(m & ((1u << lane) - 1u));
                    entA[pos] = make_float4(-(float)row, -(float)row,
                                            -(float)col, -(float)col);
                    float* wp = reinterpret_cast<float*>(&entW[pos >> 1]);
                    const int o = (pos & 1) * 2;
                    wp[o]     = v;
                    wp[o + 1] = v;
                }
                p += __popc(m);
            }
        }
    }
    // Tail fix: if K odd, slot K gets a safe dummy (coords (0,0), weight 0).
    // den at (0,0) is fi^2+fj^2+c > 0 for every lane, and w1=0 makes the
    // pair's second term exactly 0 (num = w0*b + 0*a; acc += num*rcp(a*b)).
    if (tid == 0 && (sK & 1)) {
        entA[sK] = make_float4(0.f, 0.f, 0.f, 0.f);
        float* wp = reinterpret_cast<float*>(&entW[sK >> 1]);
        wp[2] = 0.f;
        wp[3] = 0.f;
    }
    __syncthreads();

    const float z0 = CENTERF - sqrtf(r2_0) + EPSF;
    const float z1 = CENTERF - sqrtf(r2_1) + EPSF;
    const float c00  = fmaf(z0, z0, EPSF * EPSF);
    const float c01v = fmaf(z1, z1, EPSF * EPSF);

    const unsigned long long fi01 = pk2(fi0, fi0 + 1.0f);
    const unsigned long long fj2  = pk2(fj, fj);
    const unsigned long long c01  = pk2(c00, c01v);

    const int K  = sK;
    const int Kp = (K + 1) >> 1;                  // source pairs
    float f0 = 0.0f, f1 = 0.0f;

    // ---- Phase 2: paired-reciprocal f32x2 core (R16-proven) ----
    {
        unsigned long long acc = pk2(0.0f, 0.0f);
        const int nfull = (Kp > wid) ? (Kp - wid + 31) / 32 : 0;
        const int nb8 = nfull >> 3;
        const float4* pA = entA + 2 * wid;
        const float4* pW = entW + wid;

        for (int b8 = 0; b8 < nb8; b8++) {
            #pragma unroll
            for (int u = 0; u < 8; u++) {
                const float4 eA0 = pA[u * 64];        // (-bi0,-bi0,-bj0,-bj0)
                const float4 eA1 = pA[u * 64 + 1];    // (-bi1,-bi1,-bj1,-bj1)
                const float4 eW  = pW[u * 32];        // ( w0,  w0,  w1,  w1)
                const unsigned long long A0i = pk2(eA0.x, eA0.y);
                const unsigned long long A0j = pk2(eA0.z, eA0.w);
                const unsigned long long A1i = pk2(eA1.x, eA1.y);
                const unsigned long long A1j = pk2(eA1.z, eA1.w);
                const unsigned long long W0  = pk2(eW.x, eW.y);
                const unsigned long long W1  = pk2(eW.z, eW.w);

                unsigned long long di0, dj0, u0, a, di1, dj1, u1, bb;
                ADD2(di0, fi01, A0i);
                ADD2(dj0, fj2,  A0j);
                FMA2(u0, dj0, dj0, c01);
                FMA2(a,  di0, di0, u0);
                ADD2(di1, fi01, A1i);
                ADD2(dj1, fj2,  A1j);
                FMA2(u1, dj1, dj1, c01);
                FMA2(bb, di1, di1, u1);

                unsigned long long P, m, num, inv;
                MUL2(P, a, bb);
                MUL2(m, W0, bb);
                FMA2(num, W1, a, m);
                RCP2(inv, P);
                FMA2(acc, num, inv, acc);
            }
            pA += 512;
            pW += 256;
        }
        for (int r = nb8 * 8; r < nfull; r++) {
            const float4 eA0 = pA[0];
            const float4 eA1 = pA[1];
            const float4 eW  = pW[0];
            pA += 64; pW += 32;
            const unsigned long long A0i = pk2(eA0.x, eA0.y);
            const unsigned long long A0j = pk2(eA0.z, eA0.w);
            const unsigned long long A1i = pk2(eA1.x, eA1.y);
            const unsigned long long A1j = pk2(eA1.z, eA1.w);
            const unsigned long long W0  = pk2(eW.x, eW.y);
            const unsigned long long W1  = pk2(eW.z, eW.w);

            unsigned long long di0, dj0, u0, a, di1, dj1, u1, bb;
            ADD2(di0, fi01, A0i);
            ADD2(dj0, fj2,  A0j);
            FMA2(u0, dj0, dj0, c01);
            FMA2(a,  di0, di0, u0);
            ADD2(di1, fi01, A1i);
            ADD2(dj1, fj2,  A1j);
            FMA2(u1, dj1, dj1, c01);
            FMA2(bb, di1, di1, u1);

            unsigned long long P, m, num, inv;
            MUL2(P, a, bb);
            MUL2(m, W0, bb);
            FMA2(num, W1, a, m);
            RCP2(inv, P);
            FMA2(acc, num, inv, acc);
        }
        unpk2(acc, f0, f1);
    }

    red[wid * 64 + lane]      = f0;
    red[wid * 64 + 32 + lane] = f1;
    __syncthreads();

    // ---- Phase 3: reduce + store ----
    if (tid < 64) {
        const int k = tid >> 5;                   // which of the two i-rows
        const int l = tid & 31;
        float s = 0.0f;
        #pragma unroll
        for (int w = 0; w < NWARPS; w++) s += red[w * 64 + k * 32 + l];

        const int jj = J0 + 32 * g + l;
        if (jj < RES) {
            const int ii  = i0 + k;
            const int di  = ii - 48, dj = jj - 48;
            const float bv = b[ii * RES + jj];
            out[ii * RES + jj] = (di * di + dj * dj >= 2209) ? bv : s;
        }
    }
}

// ---------------------------------------------------------------------------
extern "C" void kernel_launch(void* const* d_in, const int* in_sizes, int n_in,
                              void* d_out, int out_size) {
    (void)in_sizes; (void)n_in; (void)out_size;
    const float* b   = (const float*)d_in[0];
    float*       out = (float*)d_out;

    const int smem_bytes = (CAPS + CAPP) * (int)sizeof(float4);  // 221184
    cudaFuncSetAttribute(fused_kernel,
                         cudaFuncAttributeMaxDynamicSharedMemorySize, smem_bytes);

    fused_kernel<<<144, 1024, smem_bytes>>>(b, out);
}